// round 15
// baseline (speedup 1.0000x reference)
#include <cuda_runtime.h>
#include <cuda_fp16.h>
#include <math.h>
#include <stdint.h>

// B=2, H=16, S=2048, DK=64
// Inputs: Q[B,H,S,DK] f32, K[B,H,S,DK] f32, V[B,H,S,DK] f32, mask[B,1,S,S] i32
// Output: concat( O[B,H,S,DK] f32, W[B,H,S,S] f32 )

#define BATCH 2
#define HEADS 16
#define SEQ   2048
#define DKDIM 64
#define NELEM ((size_t)BATCH * HEADS * SEQ * DKDIM)       // 4,194,304
#define NMASK ((size_t)BATCH * SEQ * SEQ)                 // 8,388,608

#define HST 72   // half-element stride (144B rows; cp.async aligned, ldmatrix conflict-free)

// 0.125 * log2(e)
#define SCALE_L2E 0.18033688011112042f

__device__ __half g_Qh[NELEM];
__device__ __half g_Kh[NELEM];
__device__ __half g_Vh[NELEM];
__device__ __half g_Mh[NMASK];                            // mask as fp16 {0,1}
__device__ __half g_E[(size_t)BATCH * HEADS * SEQ * SEQ]; // unnormalized exp, fp16
__device__ float  g_inv[(size_t)BATCH * HEADS * SEQ];

// ---------------------------------------------------------------------------
__device__ __forceinline__ uint32_t pack2(float a, float b) {
    __half2 h = __floats2half2_rn(a, b);
    return *(uint32_t*)&h;
}

__device__ __forceinline__ float fexp2(float x) {
    float y;
    asm("ex2.approx.ftz.f32 %0, %1;" : "=f"(y) : "f"(x));
    return y;
}

__device__ __forceinline__ void cp16(void* smem, const void* gmem) {
    uint32_t s = (uint32_t)__cvta_generic_to_shared(smem);
    asm volatile("cp.async.cg.shared.global [%0], [%1], 16;" :: "r"(s), "l"(gmem));
}
__device__ __forceinline__ void cp_commit() {
    asm volatile("cp.async.commit_group;");
}
__device__ __forceinline__ void cp_wait0() {
    asm volatile("cp.async.wait_group 0;");
}

__device__ __forceinline__ void ldsm4(uint32_t r[4], const __half* p) {
    uint32_t addr = (uint32_t)__cvta_generic_to_shared(p);
    asm volatile("ldmatrix.sync.aligned.m8n8.x4.shared.b16 {%0,%1,%2,%3}, [%4];"
                 : "=r"(r[0]), "=r"(r[1]), "=r"(r[2]), "=r"(r[3]) : "r"(addr));
}
__device__ __forceinline__ void ldsm4t(uint32_t r[4], const __half* p) {
    uint32_t addr = (uint32_t)__cvta_generic_to_shared(p);
    asm volatile("ldmatrix.sync.aligned.m8n8.x4.trans.shared.b16 {%0,%1,%2,%3}, [%4];"
                 : "=r"(r[0]), "=r"(r[1]), "=r"(r[2]), "=r"(r[3]) : "r"(addr));
}
__device__ __forceinline__ void mma_f16(float c[4], const uint32_t a[4],
                                        uint32_t b0, uint32_t b1) {
    asm volatile(
        "mma.sync.aligned.m16n8k16.row.col.f32.f16.f16.f32 "
        "{%0,%1,%2,%3}, {%4,%5,%6,%7}, {%8,%9}, {%0,%1,%2,%3};\n"
        : "+f"(c[0]), "+f"(c[1]), "+f"(c[2]), "+f"(c[3])
        : "r"(a[0]), "r"(a[1]), "r"(a[2]), "r"(a[3]), "r"(b0), "r"(b1));
}

// ---------------------------------------------------------------------------
// Merged pre-convert: Q/K/V f32 -> fp16 (blocks < 2048) + mask -> fp16 {0,1}.
// ---------------------------------------------------------------------------
__global__ __launch_bounds__(256)
void convert_all_kernel(const float* __restrict__ Q,
                        const float* __restrict__ K,
                        const float* __restrict__ V,
                        const int*   __restrict__ mask)
{
    const size_t i = ((size_t)blockIdx.x * 256 + threadIdx.x) * 8;
    if (blockIdx.x < NELEM / (256 * 8)) {
        {
            float4 a = *(const float4*)(Q + i), b = *(const float4*)(Q + i + 4);
            uint4 u = { pack2(a.x, a.y), pack2(a.z, a.w), pack2(b.x, b.y), pack2(b.z, b.w) };
            *(uint4*)(g_Qh + i) = u;
        }
        {
            float4 a = *(const float4*)(K + i), b = *(const float4*)(K + i + 4);
            uint4 u = { pack2(a.x, a.y), pack2(a.z, a.w), pack2(b.x, b.y), pack2(b.z, b.w) };
            *(uint4*)(g_Kh + i) = u;
        }
        {
            float4 a = *(const float4*)(V + i), b = *(const float4*)(V + i + 4);
            uint4 u = { pack2(a.x, a.y), pack2(a.z, a.w), pack2(b.x, b.y), pack2(b.z, b.w) };
            *(uint4*)(g_Vh + i) = u;
        }
    }
    {
        int4 a = *(const int4*)(mask + i);
        int4 b = *(const int4*)(mask + i + 4);
        uint4 u;
        u.x = pack2(a.x ? 1.f : 0.f, a.y ? 1.f : 0.f);
        u.y = pack2(a.z ? 1.f : 0.f, a.w ? 1.f : 0.f);
        u.z = pack2(b.x ? 1.f : 0.f, b.y ? 1.f : 0.f);
        u.w = pack2(b.z ? 1.f : 0.f, b.w ? 1.f : 0.f);
        *(uint4*)(g_Mh + i) = u;
    }
}

// ---------------------------------------------------------------------------
// Pass A (flash-style register P-reuse, 2 tiles per barrier, Q-frags hoisted).
// 8 warps each own a 16-row q strip of the 128-row q tile.
// Loop over 16 pairs of 64-wide k-tiles:
//   [wait+sync once]  then for each of 2 tiles:
//   mma1 S=QK^T (Q-frags in regs) ; e = ex2(S*c)*m ; STG fp16 e -> g_E ;
//   repack e as A-frags ; mma2 accO += e @ V.
// End: inv=1/rowsum -> g_inv, O=accO*inv.
// K/V in 4 tile slots (2 resident pairs), cp.async double-pair buffering.
// ---------------------------------------------------------------------------
__global__ __launch_bounds__(256, 2)
void sdpa_fused_kernel(float* __restrict__ O)
{
    extern __shared__ __align__(16) char smraw[];
    __half* Qs = (__half*)smraw;              // [128][HST] (staging only)
    __half* Ks = Qs + 128 * HST;              // [4][64][HST]
    __half* Vs = Ks + 4 * 64 * HST;           // [4][64][HST]

    const int bh   = blockIdx.y;
    const int b    = bh >> 4;
    const int q0   = blockIdx.x * 128;
    const int tid  = threadIdx.x;
    const int lane = tid & 31;
    const int warp = tid >> 5;    // 0..7, owns q rows [warp*16, +16)
    const int gid  = lane >> 2;   // 0..7
    const int tig  = lane & 3;    // 0..3

    const __half* Qp = g_Qh + ((size_t)bh * SEQ + q0) * DKDIM;
    const __half* Kp = g_Kh + (size_t)bh * SEQ * DKDIM;
    const __half* Vp = g_Vh + (size_t)bh * SEQ * DKDIM;

    const int crow = tid >> 3;   // 0..31
    const int cgrp = tid & 7;

    // ldmatrix lane patterns
    const int a_row  = (lane & 15);
    const int a_col  = (lane >> 4) << 3;
    const int bk_row = ((lane >> 4) << 3) + (lane & 7);
    const int bk_col = ((lane >> 3) & 1) << 3;
    const int bv_row = (((lane >> 3) & 1) << 3) + (lane & 7);
    const int bv_col = (lane >> 4) << 3;

    // per-thread global row bases
    const int rl0 = warp * 16 + gid;
    const int rl1 = rl0 + 8;
    const __half* mrow0 = g_Mh + ((size_t)b * SEQ + q0 + rl0) * SEQ;
    const __half* mrow1 = g_Mh + ((size_t)b * SEQ + q0 + rl1) * SEQ;
    __half* erow0 = g_E + ((size_t)bh * SEQ + q0 + rl0) * SEQ;
    __half* erow1 = g_E + ((size_t)bh * SEQ + q0 + rl1) * SEQ;

    // ---------------- prologue: Q + tiles 0,1 (one group) ----------------
    #pragma unroll
    for (int it = 0; it < 4; it++) {
        const int id  = tid + it * 256;
        const int row = id >> 3;
        cp16(Qs + row * HST + cgrp * 8, Qp + row * DKDIM + cgrp * 8);
    }
    #pragma unroll
    for (int t = 0; t < 2; t++) {
        const __half* Kt = Kp + (size_t)t * 64 * DKDIM;
        const __half* Vt = Vp + (size_t)t * 64 * DKDIM;
        #pragma unroll
        for (int it = 0; it < 2; it++) {
            const int row = crow + 32 * it;
            cp16(Ks + (t * 64 + row) * HST + cgrp * 8, Kt + (size_t)row * DKDIM + cgrp * 8);
            cp16(Vs + (t * 64 + row) * HST + cgrp * 8, Vt + (size_t)row * DKDIM + cgrp * 8);
        }
    }
    cp_commit();
    cp_wait0();
    __syncthreads();

    // hoist Q fragments (loop-invariant)
    uint32_t qa[4][4];
    #pragma unroll
    for (int d = 0; d < 4; d++)
        ldsm4(qa[d], Qs + (warp * 16 + a_row) * HST + d * 16 + a_col);

    float rsum0 = 0.f, rsum1 = 0.f;

    float accO[8][4];
    #pragma unroll
    for (int j = 0; j < 8; j++)
        #pragma unroll
        for (int t = 0; t < 4; t++) accO[j][t] = 0.f;

    for (int kt2 = 0; kt2 < 16; kt2++) {
        if (kt2 > 0) {
            cp_wait0();       // pair kt2 resident
            __syncthreads();  // all warps done with previous pair's slots
        }

        // prefetch pair kt2+1 into the slots freed at kt2-1
        if (kt2 + 1 < 16) {
            const int nb = ((kt2 + 1) & 1) * 2;
            #pragma unroll
            for (int t = 0; t < 2; t++) {
                const int ktn = 2 * (kt2 + 1) + t;
                const __half* Kn = Kp + (size_t)ktn * 64 * DKDIM;
                const __half* Vn = Vp + (size_t)ktn * 64 * DKDIM;
                #pragma unroll
                for (int it = 0; it < 2; it++) {
                    const int row = crow + 32 * it;
                    cp16(Ks + ((nb + t) * 64 + row) * HST + cgrp * 8, Kn + (size_t)row * DKDIM + cgrp * 8);
                    cp16(Vs + ((nb + t) * 64 + row) * HST + cgrp * 8, Vn + (size_t)row * DKDIM + cgrp * 8);
                }
            }
            cp_commit();
        }

        // ---- compute the 2 tiles of this pair ----
        #pragma unroll
        for (int sub = 0; sub < 2; sub++) {
            const int kt   = 2 * kt2 + sub;
            const int slot = (kt2 & 1) * 2 + sub;
            const __half* Kb = Ks + slot * 64 * HST;
            const __half* Vb = Vs + slot * 64 * HST;

            // mma1: S(16q x 64k) = Q @ K^T
            float accS[8][4];
            #pragma unroll
            for (int j = 0; j < 8; j++)
                #pragma unroll
                for (int t = 0; t < 4; t++) accS[j][t] = 0.f;

            #pragma unroll
            for (int d = 0; d < 4; d++) {
                #pragma unroll
                for (int nb = 0; nb < 4; nb++) {
                    uint32_t bb[4];
                    ldsm4(bb, Kb + (nb * 16 + bk_row) * HST + d * 16 + bk_col);
                    mma_f16(accS[nb * 2 + 0], qa[d], bb[0], bb[1]);
                    mma_f16(accS[nb * 2 + 1], qa[d], bb[2], bb[3]);
                }
            }

            // epilogue: e = ex2(s*c)*m -> g_E; repack as A-frags
            uint32_t pk_lo[8], pk_hi[8];
            {
                const __half* m0 = mrow0 + kt * 64;
                const __half* m1 = mrow1 + kt * 64;
                __half* e0p = erow0 + kt * 64;
                __half* e1p = erow1 + kt * 64;
                #pragma unroll
                for (int j = 0; j < 8; j++) {
                    const int c = j * 8 + 2 * tig;
                    const uint32_t mm0 = *(const uint32_t*)(m0 + c);
                    const uint32_t mm1 = *(const uint32_t*)(m1 + c);
                    float2 mf0 = __half22float2(*(const __half2*)&mm0);
                    float2 mf1 = __half22float2(*(const __half2*)&mm1);
                    float e00 = fexp2(accS[j][0] * SCALE_L2E) * mf0.x;
                    float e01 = fexp2(accS[j][1] * SCALE_L2E) * mf0.y;
                    float e10 = fexp2(accS[j][2] * SCALE_L2E) * mf1.x;
                    float e11 = fexp2(accS[j][3] * SCALE_L2E) * mf1.y;
                    pk_lo[j] = pack2(e00, e01);
                    pk_hi[j] = pack2(e10, e11);
                    *(uint32_t*)(e0p + c) = pk_lo[j];
                    *(uint32_t*)(e1p + c) = pk_hi[j];
                    rsum0 += e00 + e01;
                    rsum1 += e10 + e11;
                }
            }

            // mma2: accO += e @ V  (A from registers)
            #pragma unroll
            for (int cch = 0; cch < 4; cch++) {
                uint32_t a[4] = { pk_lo[2 * cch], pk_hi[2 * cch],
                                  pk_lo[2 * cch + 1], pk_hi[2 * cch + 1] };
                const int k0 = cch * 16;
                #pragma unroll
                for (int nb = 0; nb < 4; nb++) {
                    uint32_t bb[4];
                    ldsm4t(bb, Vb + (k0 + bv_row) * HST + nb * 16 + bv_col);
                    mma_f16(accO[nb * 2 + 0], a, bb[0], bb[1]);
                    mma_f16(accO[nb * 2 + 1], a, bb[2], bb[3]);
                }
            }
        }
    }

    // ---- warp-private rowsums -> inv (quad all-reduce) ----
    rsum0 += __shfl_xor_sync(0xffffffffu, rsum0, 1);
    rsum0 += __shfl_xor_sync(0xffffffffu, rsum0, 2);
    rsum1 += __shfl_xor_sync(0xffffffffu, rsum1, 1);
    rsum1 += __shfl_xor_sync(0xffffffffu, rsum1, 2);
    const float inv0 = 1.0f / rsum0;
    const float inv1 = 1.0f / rsum1;
    if (tig == 0) {
        g_inv[(size_t)bh * SEQ + q0 + rl0] = inv0;
        g_inv[(size_t)bh * SEQ + q0 + rl1] = inv1;
    }

    // ---- store O = accO * inv ----
    float* orow0 = O + ((size_t)bh * SEQ + q0 + rl0) * DKDIM;
    float* orow1 = O + ((size_t)bh * SEQ + q0 + rl1) * DKDIM;
    #pragma unroll
    for (int j = 0; j < 8; j++) {
        const int c = j * 8 + 2 * tig;
        float2 v0 = { accO[j][0] * inv0, accO[j][1] * inv0 };
        float2 v1 = { accO[j][2] * inv1, accO[j][3] * inv1 };
        *(float2*)(orow0 + c) = v0;
        *(float2*)(orow1 + c) = v1;
    }
}

// ---------------------------------------------------------------------------
// Pass B: W = fp16(e) * inv, streaming. One block per row.
// ---------------------------------------------------------------------------
__global__ __launch_bounds__(256)
void sdpa_normw_kernel(float* __restrict__ Wm)
{
    const size_t row = blockIdx.x;
    const float inv = g_inv[row];
    const uint4* ep = (const uint4*)(g_E + row * SEQ);
    uint4 u = ep[threadIdx.x];

    float2 f0 = __half22float2(*(__half2*)&u.x);
    float2 f1 = __half22float2(*(__half2*)&u.y);
    float2 f2 = __half22float2(*(__half2*)&u.z);
    float2 f3 = __half22float2(*(__half2*)&u.w);

    float4 o0 = { f0.x * inv, f0.y * inv, f1.x * inv, f1.y * inv };
    float4 o1 = { f2.x * inv, f2.y * inv, f3.x * inv, f3.y * inv };

    float4* wp = (float4*)(Wm + row * SEQ) + threadIdx.x * 2;
    wp[0] = o0;
    wp[1] = o1;
}

// ---------------------------------------------------------------------------
extern "C" void kernel_launch(void* const* d_in, const int* in_sizes, int n_in,
                              void* d_out, int out_size)
{
    const float* Q    = (const float*)d_in[0];
    const float* K    = (const float*)d_in[1];
    const float* V    = (const float*)d_in[2];
    const int*   mask = (const int*)  d_in[3];

    float* O = (float*)d_out;                                        // [B,H,S,DK]
    float* W = (float*)d_out + (size_t)BATCH * HEADS * SEQ * DKDIM;  // [B,H,S,S]

    const int smem = (128 * HST + 4 * 64 * HST + 4 * 64 * HST) * 2;  // 92,160 B
    cudaFuncSetAttribute(sdpa_fused_kernel,
                         cudaFuncAttributeMaxDynamicSharedMemorySize, smem);

    {
        convert_all_kernel<<<NMASK / (256 * 8), 256>>>(Q, K, V, mask);
    }
    {
        dim3 grid(SEQ / 128, BATCH * HEADS);
        sdpa_fused_kernel<<<grid, 256, smem>>>(O);
    }
    {
        dim3 grid(BATCH * HEADS * SEQ);
        sdpa_normw_kernel<<<grid, 256>>>(W);
    }
}

// round 16
// speedup vs baseline: 1.0508x; 1.0508x over previous
#include <cuda_runtime.h>
#include <cuda_fp16.h>
#include <math.h>
#include <stdint.h>

// B=2, H=16, S=2048, DK=64
// Inputs: Q[B,H,S,DK] f32, K[B,H,S,DK] f32, V[B,H,S,DK] f32, mask[B,1,S,S] i32
// Output: concat( O[B,H,S,DK] f32, W[B,H,S,S] f32 )

#define BATCH 2
#define HEADS 16
#define SEQ   2048
#define DKDIM 64
#define NELEM ((size_t)BATCH * HEADS * SEQ * DKDIM)       // 4,194,304
#define NMASK ((size_t)BATCH * SEQ * SEQ)                 // 8,388,608

#define HST 72   // half-element stride (144B rows; cp.async aligned, ldmatrix conflict-free)

// 0.125 * log2(e)
#define SCALE_L2E 0.18033688011112042f

__device__ __half g_Qh[NELEM];
__device__ __half g_Kh[NELEM];
__device__ __half g_Vh[NELEM];
__device__ __half g_Mh[NMASK];                            // mask as fp16 {0,1}
__device__ __half g_E[(size_t)BATCH * HEADS * SEQ * SEQ]; // unnormalized exp, fp16
__device__ float  g_inv[(size_t)BATCH * HEADS * SEQ];

// ---------------------------------------------------------------------------
__device__ __forceinline__ uint32_t pack2(float a, float b) {
    __half2 h = __floats2half2_rn(a, b);
    return *(uint32_t*)&h;
}

// one-instruction pack: {lo, hi} halves from two floats
__device__ __forceinline__ uint32_t packcvt(float lo, float hi) {
    uint32_t d;
    asm("cvt.rn.f16x2.f32 %0, %1, %2;" : "=r"(d) : "f"(hi), "f"(lo));
    return d;
}
// paired half2 exp2 — ONE MUFU op for two elements
__device__ __forceinline__ uint32_t ex2h2(uint32_t x) {
    uint32_t d;
    asm("ex2.approx.f16x2 %0, %1;" : "=r"(d) : "r"(x));
    return d;
}
__device__ __forceinline__ uint32_t mulh2(uint32_t a, uint32_t b) {
    uint32_t d;
    asm("mul.rn.f16x2 %0, %1, %2;" : "=r"(d) : "r"(a), "r"(b));
    return d;
}

__device__ __forceinline__ void cp16(void* smem, const void* gmem) {
    uint32_t s = (uint32_t)__cvta_generic_to_shared(smem);
    asm volatile("cp.async.cg.shared.global [%0], [%1], 16;" :: "r"(s), "l"(gmem));
}
__device__ __forceinline__ void cp_commit() {
    asm volatile("cp.async.commit_group;");
}
__device__ __forceinline__ void cp_wait0() {
    asm volatile("cp.async.wait_group 0;");
}

__device__ __forceinline__ void ldsm4(uint32_t r[4], const __half* p) {
    uint32_t addr = (uint32_t)__cvta_generic_to_shared(p);
    asm volatile("ldmatrix.sync.aligned.m8n8.x4.shared.b16 {%0,%1,%2,%3}, [%4];"
                 : "=r"(r[0]), "=r"(r[1]), "=r"(r[2]), "=r"(r[3]) : "r"(addr));
}
__device__ __forceinline__ void ldsm4t(uint32_t r[4], const __half* p) {
    uint32_t addr = (uint32_t)__cvta_generic_to_shared(p);
    asm volatile("ldmatrix.sync.aligned.m8n8.x4.trans.shared.b16 {%0,%1,%2,%3}, [%4];"
                 : "=r"(r[0]), "=r"(r[1]), "=r"(r[2]), "=r"(r[3]) : "r"(addr));
}
__device__ __forceinline__ void mma_f16(float c[4], const uint32_t a[4],
                                        uint32_t b0, uint32_t b1) {
    asm volatile(
        "mma.sync.aligned.m16n8k16.row.col.f32.f16.f16.f32 "
        "{%0,%1,%2,%3}, {%4,%5,%6,%7}, {%8,%9}, {%0,%1,%2,%3};\n"
        : "+f"(c[0]), "+f"(c[1]), "+f"(c[2]), "+f"(c[3])
        : "r"(a[0]), "r"(a[1]), "r"(a[2]), "r"(a[3]), "r"(b0), "r"(b1));
}

// ---------------------------------------------------------------------------
// Pre-convert Q/K/V f32 -> fp16.
// ---------------------------------------------------------------------------
__global__ __launch_bounds__(256)
void convert_kernel(const float* __restrict__ Q,
                    const float* __restrict__ K,
                    const float* __restrict__ V)
{
    const size_t i = ((size_t)blockIdx.x * 256 + threadIdx.x) * 8;
    {
        float4 a = *(const float4*)(Q + i), b = *(const float4*)(Q + i + 4);
        uint4 u = { pack2(a.x, a.y), pack2(a.z, a.w), pack2(b.x, b.y), pack2(b.z, b.w) };
        *(uint4*)(g_Qh + i) = u;
    }
    {
        float4 a = *(const float4*)(K + i), b = *(const float4*)(K + i + 4);
        uint4 u = { pack2(a.x, a.y), pack2(a.z, a.w), pack2(b.x, b.y), pack2(b.z, b.w) };
        *(uint4*)(g_Kh + i) = u;
    }
    {
        float4 a = *(const float4*)(V + i), b = *(const float4*)(V + i + 4);
        uint4 u = { pack2(a.x, a.y), pack2(a.z, a.w), pack2(b.x, b.y), pack2(b.z, b.w) };
        *(uint4*)(g_Vh + i) = u;
    }
}

// Mask int32 -> fp16 {0,1}
__global__ __launch_bounds__(256)
void maskconv_kernel(const int* __restrict__ mask)
{
    const size_t i = ((size_t)blockIdx.x * 256 + threadIdx.x) * 8;
    int4 a = *(const int4*)(mask + i);
    int4 b = *(const int4*)(mask + i + 4);
    uint4 u;
    u.x = pack2(a.x ? 1.f : 0.f, a.y ? 1.f : 0.f);
    u.y = pack2(a.z ? 1.f : 0.f, a.w ? 1.f : 0.f);
    u.z = pack2(b.x ? 1.f : 0.f, b.y ? 1.f : 0.f);
    u.w = pack2(b.z ? 1.f : 0.f, b.w ? 1.f : 0.f);
    *(uint4*)(g_Mh + i) = u;
}

// ---------------------------------------------------------------------------
// Pass A (R13 structure, f16x2-exp epilogue): 8 warps each own a 16-row q
// strip. Loop 32 k-tiles of 64:
//   mma1 S(16x64) = Q K^T ; pk = ex2h2(cvt(S*c)) * mask ; STG pk -> g_E ;
//   pk reused as mma2 A-frags (register reuse) ; mma2 accO += e @ V.
// One block sync per iteration (cp.async buffers). Rowsums warp-private.
// ---------------------------------------------------------------------------
__global__ __launch_bounds__(256, 2)
void sdpa_fused_kernel(float* __restrict__ O)
{
    extern __shared__ __align__(16) char smraw[];
    __half* Qs = (__half*)smraw;              // [128][HST]
    __half* Ks = Qs + 128 * HST;              // [2][64][HST]
    __half* Vs = Ks + 2 * 64 * HST;           // [2][64][HST]

    const int bh   = blockIdx.y;
    const int b    = bh >> 4;
    const int q0   = blockIdx.x * 128;
    const int tid  = threadIdx.x;
    const int lane = tid & 31;
    const int warp = tid >> 5;    // 0..7, owns q rows [warp*16, +16)
    const int gid  = lane >> 2;   // 0..7
    const int tig  = lane & 3;    // 0..3

    const __half* Qp = g_Qh + ((size_t)bh * SEQ + q0) * DKDIM;
    const __half* Kp = g_Kh + (size_t)bh * SEQ * DKDIM;
    const __half* Vp = g_Vh + (size_t)bh * SEQ * DKDIM;

    const int crow = tid >> 3;   // 0..31
    const int cgrp = tid & 7;

    // prologue: Q tile + K0/V0, one cp.async group
    #pragma unroll
    for (int it = 0; it < 4; it++) {
        const int id  = tid + it * 256;
        const int row = id >> 3;
        cp16(Qs + row * HST + cgrp * 8, Qp + row * DKDIM + cgrp * 8);
    }
    #pragma unroll
    for (int it = 0; it < 2; it++) {
        const int row = crow + 32 * it;
        cp16(Ks + row * HST + cgrp * 8, Kp + (size_t)row * DKDIM + cgrp * 8);
        cp16(Vs + row * HST + cgrp * 8, Vp + (size_t)row * DKDIM + cgrp * 8);
    }
    cp_commit();

    float rsum0 = 0.f, rsum1 = 0.f;     // rows warp*16+gid, +8

    float accO[8][4];
    #pragma unroll
    for (int j = 0; j < 8; j++)
        #pragma unroll
        for (int t = 0; t < 4; t++) accO[j][t] = 0.f;

    // ldmatrix lane patterns
    const int a_row  = (lane & 15);
    const int a_col  = (lane >> 4) << 3;
    const int bk_row = ((lane >> 4) << 3) + (lane & 7);
    const int bk_col = ((lane >> 3) & 1) << 3;
    const int bv_row = (((lane >> 3) & 1) << 3) + (lane & 7);
    const int bv_col = (lane >> 4) << 3;

    // per-thread global row bases
    const int rl0 = warp * 16 + gid;
    const int rl1 = rl0 + 8;
    const __half* mrow0 = g_Mh + ((size_t)b * SEQ + q0 + rl0) * SEQ;
    const __half* mrow1 = g_Mh + ((size_t)b * SEQ + q0 + rl1) * SEQ;
    __half* erow0 = g_E + ((size_t)bh * SEQ + q0 + rl0) * SEQ;
    __half* erow1 = g_E + ((size_t)bh * SEQ + q0 + rl1) * SEQ;

    for (int kt = 0; kt < 32; kt++) {
        const int buf = kt & 1;

        cp_wait0();          // tile kt resident
        __syncthreads();     // all warps done with kt-1 buffers

        if (kt + 1 < 32) {
            const int nb = (kt + 1) & 1;
            const __half* Kn = Kp + (size_t)(kt + 1) * 64 * DKDIM;
            const __half* Vn = Vp + (size_t)(kt + 1) * 64 * DKDIM;
            #pragma unroll
            for (int it = 0; it < 2; it++) {
                const int row = crow + 32 * it;
                cp16(Ks + (nb * 64 + row) * HST + cgrp * 8, Kn + (size_t)row * DKDIM + cgrp * 8);
                cp16(Vs + (nb * 64 + row) * HST + cgrp * 8, Vn + (size_t)row * DKDIM + cgrp * 8);
            }
            cp_commit();
        }

        const __half* Kb = Ks + buf * 64 * HST;
        const __half* Vb = Vs + buf * 64 * HST;

        // ---- mma1: S(16q x 64k) = Q @ K^T ----
        float accS[8][4];
        #pragma unroll
        for (int j = 0; j < 8; j++)
            #pragma unroll
            for (int t = 0; t < 4; t++) accS[j][t] = 0.f;

        #pragma unroll
        for (int d0 = 0; d0 < DKDIM; d0 += 16) {
            uint32_t a[4];
            ldsm4(a, Qs + (warp * 16 + a_row) * HST + d0 + a_col);
            #pragma unroll
            for (int nb = 0; nb < 4; nb++) {
                uint32_t bb[4];
                ldsm4(bb, Kb + (nb * 16 + bk_row) * HST + d0 + bk_col);
                mma_f16(accS[nb * 2 + 0], a, bb[0], bb[1]);
                mma_f16(accS[nb * 2 + 1], a, bb[2], bb[3]);
            }
        }

        // ---- epilogue: pk = ex2.f16x2(S*c) * mask -> g_E + A-frags ----
        uint32_t pk_lo[8], pk_hi[8];
        {
            const __half* m0 = mrow0 + kt * 64;
            const __half* m1 = mrow1 + kt * 64;
            __half* e0p = erow0 + kt * 64;
            __half* e1p = erow1 + kt * 64;
            #pragma unroll
            for (int j = 0; j < 8; j++) {
                const int c = j * 8 + 2 * tig;
                const uint32_t mm0 = *(const uint32_t*)(m0 + c);
                const uint32_t mm1 = *(const uint32_t*)(m1 + c);
                // scale in fp32 (accurate), pack to half2, ONE MUFU for 2 elems
                uint32_t x0 = packcvt(accS[j][0] * SCALE_L2E, accS[j][1] * SCALE_L2E);
                uint32_t x1 = packcvt(accS[j][2] * SCALE_L2E, accS[j][3] * SCALE_L2E);
                uint32_t p0 = mulh2(ex2h2(x0), mm0);
                uint32_t p1 = mulh2(ex2h2(x1), mm1);
                pk_lo[j] = p0;
                pk_hi[j] = p1;
                *(uint32_t*)(e0p + c) = p0;
                *(uint32_t*)(e1p + c) = p1;
                float2 ef0 = __half22float2(*(const __half2*)&p0);
                float2 ef1 = __half22float2(*(const __half2*)&p1);
                rsum0 += ef0.x + ef0.y;
                rsum1 += ef1.x + ef1.y;
            }
        }

        // ---- mma2: accO += e @ V  (A from registers) ----
        #pragma unroll
        for (int c = 0; c < 4; c++) {          // k chunks of 16
            uint32_t a[4] = { pk_lo[2 * c], pk_hi[2 * c], pk_lo[2 * c + 1], pk_hi[2 * c + 1] };
            const int k0 = c * 16;
            #pragma unroll
            for (int nb = 0; nb < 4; nb++) {
                uint32_t bb[4];
                ldsm4t(bb, Vb + (k0 + bv_row) * HST + nb * 16 + bv_col);
                mma_f16(accO[nb * 2 + 0], a, bb[0], bb[1]);
                mma_f16(accO[nb * 2 + 1], a, bb[2], bb[3]);
            }
        }
        // no further sync: next loop-top barrier covers buffer reuse
    }

    // ---- warp-private rowsums -> inv (quad all-reduce) ----
    rsum0 += __shfl_xor_sync(0xffffffffu, rsum0, 1);
    rsum0 += __shfl_xor_sync(0xffffffffu, rsum0, 2);
    rsum1 += __shfl_xor_sync(0xffffffffu, rsum1, 1);
    rsum1 += __shfl_xor_sync(0xffffffffu, rsum1, 2);
    const float inv0 = 1.0f / rsum0;
    const float inv1 = 1.0f / rsum1;
    if (tig == 0) {
        g_inv[(size_t)bh * SEQ + q0 + rl0] = inv0;
        g_inv[(size_t)bh * SEQ + q0 + rl1] = inv1;
    }

    // ---- store O = accO * inv ----
    float* orow0 = O + ((size_t)bh * SEQ + q0 + rl0) * DKDIM;
    float* orow1 = O + ((size_t)bh * SEQ + q0 + rl1) * DKDIM;
    #pragma unroll
    for (int j = 0; j < 8; j++) {
        const int c = j * 8 + 2 * tig;
        float2 v0 = { accO[j][0] * inv0, accO[j][1] * inv0 };
        float2 v1 = { accO[j][2] * inv1, accO[j][3] * inv1 };
        *(float2*)(orow0 + c) = v0;
        *(float2*)(orow1 + c) = v1;
    }
}

// ---------------------------------------------------------------------------
// Pass B: W = fp16(e) * inv, streaming. One block per row.
// ---------------------------------------------------------------------------
__global__ __launch_bounds__(256)
void sdpa_normw_kernel(float* __restrict__ Wm)
{
    const size_t row = blockIdx.x;
    const float inv = g_inv[row];
    const uint4* ep = (const uint4*)(g_E + row * SEQ);
    uint4 u = ep[threadIdx.x];

    float2 f0 = __half22float2(*(__half2*)&u.x);
    float2 f1 = __half22float2(*(__half2*)&u.y);
    float2 f2 = __half22float2(*(__half2*)&u.z);
    float2 f3 = __half22float2(*(__half2*)&u.w);

    float4 o0 = { f0.x * inv, f0.y * inv, f1.x * inv, f1.y * inv };
    float4 o1 = { f2.x * inv, f2.y * inv, f3.x * inv, f3.y * inv };

    float4* wp = (float4*)(Wm + row * SEQ) + threadIdx.x * 2;
    wp[0] = o0;
    wp[1] = o1;
}

// ---------------------------------------------------------------------------
extern "C" void kernel_launch(void* const* d_in, const int* in_sizes, int n_in,
                              void* d_out, int out_size)
{
    const float* Q    = (const float*)d_in[0];
    const float* K    = (const float*)d_in[1];
    const float* V    = (const float*)d_in[2];
    const int*   mask = (const int*)  d_in[3];

    float* O = (float*)d_out;                                        // [B,H,S,DK]
    float* W = (float*)d_out + (size_t)BATCH * HEADS * SEQ * DKDIM;  // [B,H,S,S]

    const int smem = (128 * HST + 2 * 64 * HST + 2 * 64 * HST) * 2;  // 55,296 B
    cudaFuncSetAttribute(sdpa_fused_kernel,
                         cudaFuncAttributeMaxDynamicSharedMemorySize, smem);

    {
        convert_kernel<<<NELEM / (256 * 8), 256>>>(Q, K, V);
        maskconv_kernel<<<NMASK / (256 * 8), 256>>>(mask);
    }
    {
        dim3 grid(SEQ / 128, BATCH * HEADS);
        sdpa_fused_kernel<<<grid, 256, smem>>>(O);
    }
    {
        dim3 grid(BATCH * HEADS * SEQ);
        sdpa_normw_kernel<<<grid, 256>>>(W);
    }
}